// round 1
// baseline (speedup 1.0000x reference)
#include <cuda_runtime.h>
#include <cuda_bf16.h>
#include <math.h>

// Problem constants (fixed by the dataset)
#define Bn   8192
#define Dn   1024
#define Hn   4096
#define On   1024
#define En   8
#define KSEL 2
// Padded capacity: each expert's row region is padded up to a multiple of 128.
#define CAP  (Bn*KSEL + En*128)   // 17408

// ---------------- device scratch (static allocation; no cudaMalloc) ----------
__device__ int   g_top[Bn * 2];       // per-token selected experts
__device__ float g_wgt[Bn * 2];       // per-token renormalized top-k weights
__device__ float g_usage[En];         // sum of gate probs per expert
__device__ int   g_count[En];         // routed-token count per expert
__device__ int   g_cursor[En];        // scatter cursors
__device__ int   g_off[En + 1];       // padded row-region offsets
__device__ int   g_tok[CAP];          // row -> token id
__device__ int   g_slot[Bn * 2];      // token -> row slot per selection
__device__ float g_h[(size_t)CAP * Hn];    // hidden activations (285 MB)
__device__ float g_out[(size_t)CAP * On];  // per-(token,expert) outputs (71 MB)
__device__ float g_avg[En * On];

// ---------------- init ----------------
__global__ void init_kernel() {
    int idx = blockIdx.x * blockDim.x + threadIdx.x;
    if (idx < CAP) g_tok[idx] = 0;
    if (idx < En) {
        g_count[idx]  = 0;
        g_cursor[idx] = 0;
        g_usage[idx]  = 0.0f;
    }
}

// ---------------- gating: one warp per token ----------------
__global__ void gate_kernel(const float* __restrict__ x,
                            const float* __restrict__ gW,
                            const float* __restrict__ gb) {
    int gwarp = (blockIdx.x * blockDim.x + threadIdx.x) >> 5;
    int lane  = threadIdx.x & 31;
    if (gwarp >= Bn) return;
    const float* xr = x + (size_t)gwarp * Dn;

    float acc[En];
#pragma unroll
    for (int e = 0; e < En; e++) acc[e] = 0.0f;

    for (int d = lane; d < Dn; d += 32) {
        float xv = xr[d];
        const float* g = gW + d * En;
#pragma unroll
        for (int e = 0; e < En; e++) acc[e] += xv * g[e];
    }
#pragma unroll
    for (int off = 16; off > 0; off >>= 1) {
#pragma unroll
        for (int e = 0; e < En; e++)
            acc[e] += __shfl_down_sync(0xffffffffu, acc[e], off);
    }
    if (lane == 0) {
        float l[En];
#pragma unroll
        for (int e = 0; e < En; e++) l[e] = acc[e] + gb[e];
        float m = l[0];
#pragma unroll
        for (int e = 1; e < En; e++) m = fmaxf(m, l[e]);
        float p[En]; float s = 0.0f;
#pragma unroll
        for (int e = 0; e < En; e++) { p[e] = expf(l[e] - m); s += p[e]; }
        float inv = 1.0f / s;

        // top-2 with lowest-index tie-break (matches lax.top_k)
        int i0 = 0;
#pragma unroll
        for (int e = 1; e < En; e++) if (p[e] > p[i0]) i0 = e;
        int i1 = (i0 == 0) ? 1 : 0;
#pragma unroll
        for (int e = 0; e < En; e++) if (e != i0 && p[e] > p[i1]) i1 = e;

        float gg0 = p[i0] * inv, gg1 = p[i1] * inv;
        float wsum = gg0 + gg1;
        g_top[2 * gwarp]     = i0;
        g_top[2 * gwarp + 1] = i1;
        g_wgt[2 * gwarp]     = gg0 / wsum;
        g_wgt[2 * gwarp + 1] = gg1 / wsum;
        atomicAdd(&g_count[i0], 1);
        atomicAdd(&g_count[i1], 1);
#pragma unroll
        for (int e = 0; e < En; e++) atomicAdd(&g_usage[e], p[e] * inv);
    }
}

// ---------------- padded prefix offsets ----------------
__global__ void offsets_kernel() {
    if (threadIdx.x == 0 && blockIdx.x == 0) {
        int o = 0;
        for (int e = 0; e < En; e++) {
            g_off[e] = o;
            o += ((g_count[e] + 127) / 128) * 128;
        }
        g_off[En] = o;
    }
}

// ---------------- scatter tokens into compact row list ----------------
__global__ void scatter_kernel() {
    int t = blockIdx.x * blockDim.x + threadIdx.x;
    if (t >= Bn) return;
#pragma unroll
    for (int j = 0; j < KSEL; j++) {
        int e = g_top[2 * t + j];
        int p = atomicAdd(&g_cursor[e], 1);
        int pos = g_off[e] + p;
        g_tok[pos] = t;
        g_slot[2 * t + j] = pos;
    }
}

// ---------------- SGEMM1: h = relu(gather(x) @ W1[e] + b1[e]) ----------------
// grid: (Hn/128, CAP/128), block 256. 128x128x16 tile, 8x8 per thread.
__global__ void __launch_bounds__(256, 2)
gemm1_kernel(const float* __restrict__ x,
             const float* __restrict__ W1,
             const float* __restrict__ b1) {
    __shared__ float As[16][128];
    __shared__ float Bs[16][128];
    __shared__ int   stok[128];
    __shared__ int   soff[En + 1];

    int m0 = blockIdx.y * 128;
    int n0 = blockIdx.x * 128;
    if (threadIdx.x <= En) soff[threadIdx.x] = g_off[threadIdx.x];
    __syncthreads();
    int total = soff[En];
    if (m0 >= total) return;
    int e = 0;
    while (m0 >= soff[e + 1]) e++;
    if (threadIdx.x < 128) stok[threadIdx.x] = g_tok[m0 + threadIdx.x];
    __syncthreads();

    const float* Wb  = W1 + (size_t)e * Dn * Hn;
    const float* b1e = b1 + (size_t)e * Hn;

    int tx = threadIdx.x & 15;   // column group
    int ty = threadIdx.x >> 4;   // row group
    float acc[8][8];
#pragma unroll
    for (int i = 0; i < 8; i++)
#pragma unroll
        for (int j = 0; j < 8; j++) acc[i][j] = 0.0f;

    for (int kt = 0; kt < Dn; kt += 16) {
#pragma unroll
        for (int it = 0; it < 2; it++) {
            int q   = threadIdx.x + it * 256;
            int row = q >> 2;
            int kq  = (q & 3) << 2;
            float4 v = *(const float4*)(x + (size_t)stok[row] * Dn + kt + kq);
            As[kq + 0][row] = v.x; As[kq + 1][row] = v.y;
            As[kq + 2][row] = v.z; As[kq + 3][row] = v.w;
        }
#pragma unroll
        for (int it = 0; it < 2; it++) {
            int q  = threadIdx.x + it * 256;
            int kr = q >> 5;
            int nq = (q & 31) << 2;
            *(float4*)&Bs[kr][nq] =
                *(const float4*)(Wb + (size_t)(kt + kr) * Hn + n0 + nq);
        }
        __syncthreads();
#pragma unroll
        for (int k = 0; k < 16; k++) {
            float a[8], b[8];
#pragma unroll
            for (int i = 0; i < 8; i++) a[i] = As[k][ty * 8 + i];
#pragma unroll
            for (int j = 0; j < 4; j++) {
                b[j]     = Bs[k][tx * 4 + j];
                b[j + 4] = Bs[k][64 + tx * 4 + j];
            }
#pragma unroll
            for (int i = 0; i < 8; i++)
#pragma unroll
                for (int j = 0; j < 8; j++) acc[i][j] += a[i] * b[j];
        }
        __syncthreads();
    }

    float4 bb0 = *(const float4*)(b1e + n0 + tx * 4);
    float4 bb1 = *(const float4*)(b1e + n0 + 64 + tx * 4);
#pragma unroll
    for (int i = 0; i < 8; i++) {
        size_t rbase = (size_t)(m0 + ty * 8 + i) * Hn + n0;
        float4 v0, v1;
        v0.x = fmaxf(acc[i][0] + bb0.x, 0.0f);
        v0.y = fmaxf(acc[i][1] + bb0.y, 0.0f);
        v0.z = fmaxf(acc[i][2] + bb0.z, 0.0f);
        v0.w = fmaxf(acc[i][3] + bb0.w, 0.0f);
        v1.x = fmaxf(acc[i][4] + bb1.x, 0.0f);
        v1.y = fmaxf(acc[i][5] + bb1.y, 0.0f);
        v1.z = fmaxf(acc[i][6] + bb1.z, 0.0f);
        v1.w = fmaxf(acc[i][7] + bb1.w, 0.0f);
        *(float4*)&g_h[rbase + tx * 4]      = v0;
        *(float4*)&g_h[rbase + 64 + tx * 4] = v1;
    }
}

// ---------------- SGEMM2: out = h @ W2[e] + b2[e] ----------------
// grid: (On/128, CAP/128)  (N-tile fastest -> h row-block L2 reuse)
__global__ void __launch_bounds__(256, 2)
gemm2_kernel(const float* __restrict__ W2,
             const float* __restrict__ b2) {
    __shared__ float As[16][128];
    __shared__ float Bs[16][128];
    __shared__ int   soff[En + 1];

    int m0 = blockIdx.y * 128;
    int n0 = blockIdx.x * 128;
    if (threadIdx.x <= En) soff[threadIdx.x] = g_off[threadIdx.x];
    __syncthreads();
    int total = soff[En];
    if (m0 >= total) return;
    int e = 0;
    while (m0 >= soff[e + 1]) e++;

    const float* Wb  = W2 + (size_t)e * Hn * On;
    const float* b2e = b2 + (size_t)e * On;

    int tx = threadIdx.x & 15;
    int ty = threadIdx.x >> 4;
    float acc[8][8];
#pragma unroll
    for (int i = 0; i < 8; i++)
#pragma unroll
        for (int j = 0; j < 8; j++) acc[i][j] = 0.0f;

    for (int kt = 0; kt < Hn; kt += 16) {
#pragma unroll
        for (int it = 0; it < 2; it++) {
            int q   = threadIdx.x + it * 256;
            int row = q >> 2;
            int kq  = (q & 3) << 2;
            float4 v = *(const float4*)(&g_h[(size_t)(m0 + row) * Hn + kt + kq]);
            As[kq + 0][row] = v.x; As[kq + 1][row] = v.y;
            As[kq + 2][row] = v.z; As[kq + 3][row] = v.w;
        }
#pragma unroll
        for (int it = 0; it < 2; it++) {
            int q  = threadIdx.x + it * 256;
            int kr = q >> 5;
            int nq = (q & 31) << 2;
            *(float4*)&Bs[kr][nq] =
                *(const float4*)(Wb + (size_t)(kt + kr) * On + n0 + nq);
        }
        __syncthreads();
#pragma unroll
        for (int k = 0; k < 16; k++) {
            float a[8], b[8];
#pragma unroll
            for (int i = 0; i < 8; i++) a[i] = As[k][ty * 8 + i];
#pragma unroll
            for (int j = 0; j < 4; j++) {
                b[j]     = Bs[k][tx * 4 + j];
                b[j + 4] = Bs[k][64 + tx * 4 + j];
            }
#pragma unroll
            for (int i = 0; i < 8; i++)
#pragma unroll
                for (int j = 0; j < 8; j++) acc[i][j] += a[i] * b[j];
        }
        __syncthreads();
    }

    float4 bb0 = *(const float4*)(b2e + n0 + tx * 4);
    float4 bb1 = *(const float4*)(b2e + n0 + 64 + tx * 4);
#pragma unroll
    for (int i = 0; i < 8; i++) {
        size_t rbase = (size_t)(m0 + ty * 8 + i) * On + n0;
        float4 v0, v1;
        v0.x = acc[i][0] + bb0.x; v0.y = acc[i][1] + bb0.y;
        v0.z = acc[i][2] + bb0.z; v0.w = acc[i][3] + bb0.w;
        v1.x = acc[i][4] + bb1.x; v1.y = acc[i][5] + bb1.y;
        v1.z = acc[i][6] + bb1.z; v1.w = acc[i][7] + bb1.w;
        *(float4*)&g_out[rbase + tx * 4]      = v0;
        *(float4*)&g_out[rbase + 64 + tx * 4] = v1;
    }
}

// ---------------- combine: final = w0*out[slot0] + w1*out[slot1] ------------
__global__ void combine_kernel(float* __restrict__ out) {
    int idx = blockIdx.x * blockDim.x + threadIdx.x;
    if (idx >= Bn * On) return;
    int t = idx >> 10;          // On == 1024
    int o = idx & (On - 1);
    int   s0 = g_slot[2 * t],     s1 = g_slot[2 * t + 1];
    float w0 = g_wgt[2 * t],      w1 = g_wgt[2 * t + 1];
    out[idx] = w0 * g_out[(size_t)s0 * On + o] + w1 * g_out[(size_t)s1 * On + o];
}

// ---------------- per-expert mean outputs (deterministic reduction) ---------
__global__ void avgs_kernel() {
    int e = blockIdx.x;
    int o = blockIdx.y * 128 + threadIdx.x;
    int off = g_off[e];
    int c   = g_count[e];
    float s = 0.0f;
    for (int r = 0; r < c; r++)
        s += g_out[(size_t)(off + r) * On + o];
    g_avg[e * On + o] = s / (float)max(c, 1);
}

// ---------------- losses ----------------
__global__ void loss_kernel(float* __restrict__ out) {
    __shared__ float red[256];
    int tid = threadIdx.x;
    float dl = 0.0f;
    for (int i = 0; i < En; i++) {
        for (int j = i + 1; j < En; j++) {
            float part = 0.0f;
            for (int o = tid; o < On; o += 256) {
                float d = g_avg[i * On + o] - g_avg[j * On + o];
                part += d * d;
            }
            red[tid] = part;
            __syncthreads();
            for (int s = 128; s > 0; s >>= 1) {
                if (tid < s) red[tid] += red[tid + s];
                __syncthreads();
            }
            if (tid == 0 && g_count[i] > 0 && g_count[j] > 0)
                dl += expf(-red[0] * 0.5f);
            __syncthreads();
        }
    }
    if (tid == 0) {
        out[(size_t)Bn * On] = dl;
        float eq = 0.0f;
        for (int e = 0; e < En; e++) {
            float u = g_usage[e] / (float)Bn - 1.0f / (float)En;
            eq += u * u;
        }
        out[(size_t)Bn * On + 1] = sqrtf(eq);
    }
}

// ---------------- launch ----------------
extern "C" void kernel_launch(void* const* d_in, const int* in_sizes, int n_in,
                              void* d_out, int out_size) {
    (void)in_sizes; (void)n_in; (void)out_size;
    const float* x  = (const float*)d_in[0];
    const float* gW = (const float*)d_in[1];
    const float* gb = (const float*)d_in[2];
    const float* W1 = (const float*)d_in[3];
    const float* b1 = (const float*)d_in[4];
    const float* W2 = (const float*)d_in[5];
    const float* b2 = (const float*)d_in[6];
    float* out = (float*)d_out;

    init_kernel<<<(CAP + 255) / 256, 256>>>();
    gate_kernel<<<Bn / 8, 256>>>(x, gW, gb);
    offsets_kernel<<<1, 32>>>();
    scatter_kernel<<<Bn / 256, 256>>>();
    gemm1_kernel<<<dim3(Hn / 128, CAP / 128), 256>>>(x, W1, b1);
    gemm2_kernel<<<dim3(On / 128, CAP / 128), 256>>>(W2, b2);
    combine_kernel<<<(Bn * On) / 256, 256>>>(out);
    avgs_kernel<<<dim3(En, On / 128), 128>>>();
    loss_kernel<<<1, 256>>>(out);
}

// round 4
// speedup vs baseline: 1.8893x; 1.8893x over previous
#include <cuda_runtime.h>
#include <cuda_bf16.h>
#include <math.h>
#include <stdint.h>

// Problem constants
#define Bn   8192
#define Dn   1024
#define Hn   4096
#define On   1024
#define En   8
#define KSEL 2
#define CAP  (Bn*KSEL + En*128)   // 17408

// ---------------- device scratch ----------------
__device__ int   g_top[Bn * 2];
__device__ float g_wgt[Bn * 2];
__device__ float g_usage[En];
__device__ int   g_count[En];
__device__ int   g_cursor[En];
__device__ int   g_off[En + 1];
__device__ int   g_tok[CAP];
__device__ int   g_slot[Bn * 2];
__device__ float g_out[(size_t)CAP * On];
__device__ float g_avg[En * On];
// bf16 hi/lo planes
__device__ __nv_bfloat16 g_xhi[(size_t)Bn * Dn];
__device__ __nv_bfloat16 g_xlo[(size_t)Bn * Dn];
__device__ __nv_bfloat16 g_w1hi[(size_t)En * Dn * Hn];
__device__ __nv_bfloat16 g_w1lo[(size_t)En * Dn * Hn];
__device__ __nv_bfloat16 g_w2hi[(size_t)En * Hn * On];
__device__ __nv_bfloat16 g_w2lo[(size_t)En * Hn * On];
__device__ __nv_bfloat16 g_hhi[(size_t)CAP * Hn];
__device__ __nv_bfloat16 g_hlo[(size_t)CAP * Hn];

// ---------------- asm helpers ----------------
__device__ __forceinline__ uint32_t smem_u32(const void* p) {
    uint32_t a;
    asm("{ .reg .u64 t; cvta.to.shared.u64 t, %1; cvt.u32.u64 %0, t; }" : "=r"(a) : "l"(p));
    return a;
}
#define CP16(dst, src) \
    asm volatile("cp.async.cg.shared.global [%0], [%1], 16;" \
                 :: "r"(dst), "l"(__cvta_generic_to_global(src)) : "memory")
#define CP_COMMIT() asm volatile("cp.async.commit_group;" ::: "memory")
#define CP_WAIT1()  asm volatile("cp.async.wait_group 1;" ::: "memory")
#define CP_WAIT0()  asm volatile("cp.async.wait_group 0;" ::: "memory")

#define LDMX4(r0,r1,r2,r3,addr) \
    asm volatile("ldmatrix.sync.aligned.m8n8.x4.shared.b16 {%0,%1,%2,%3}, [%4];" \
                 : "=r"(r0),"=r"(r1),"=r"(r2),"=r"(r3) : "r"(addr))
#define LDMX4T(r0,r1,r2,r3,addr) \
    asm volatile("ldmatrix.sync.aligned.m8n8.x4.trans.shared.b16 {%0,%1,%2,%3}, [%4];" \
                 : "=r"(r0),"=r"(r1),"=r"(r2),"=r"(r3) : "r"(addr))
#define MMA(d,a,b) \
    asm volatile("mma.sync.aligned.m16n8k16.row.col.f32.bf16.bf16.f32 " \
                 "{%0,%1,%2,%3},{%4,%5,%6,%7},{%8,%9},{%0,%1,%2,%3};" \
                 : "+f"((d)[0]),"+f"((d)[1]),"+f"((d)[2]),"+f"((d)[3]) \
                 : "r"((a)[0]),"r"((a)[1]),"r"((a)[2]),"r"((a)[3]), \
                   "r"((b)[0]),"r"((b)[1]))

__device__ __forceinline__ void split2(float a, float b, uint32_t& hi, uint32_t& lo) {
    __nv_bfloat162 h = __floats2bfloat162_rn(a, b);
    float ra = a - __bfloat162float(h.x);
    float rb = b - __bfloat162float(h.y);
    __nv_bfloat162 l = __floats2bfloat162_rn(ra, rb);
    hi = *(uint32_t*)&h; lo = *(uint32_t*)&l;
}

// ---------------- init ----------------
__global__ void init_kernel() {
    int idx = blockIdx.x * blockDim.x + threadIdx.x;
    if (idx < CAP) g_tok[idx] = 0;
    if (idx < En) { g_count[idx] = 0; g_cursor[idx] = 0; g_usage[idx] = 0.0f; }
}

// ---------------- fp32 -> bf16 hi/lo planes ----------------
__global__ void convert_kernel(const float* __restrict__ src,
                               __nv_bfloat16* __restrict__ hi,
                               __nv_bfloat16* __restrict__ lo, int n4) {
    int i = blockIdx.x * blockDim.x + threadIdx.x;
    if (i >= n4) return;
    float4 v = __ldg((const float4*)src + i);
    uint32_t h01, l01, h23, l23;
    split2(v.x, v.y, h01, l01);
    split2(v.z, v.w, h23, l23);
    ((uint2*)hi)[i] = make_uint2(h01, h23);
    ((uint2*)lo)[i] = make_uint2(l01, l23);
}

// ---------------- gating: one warp per token ----------------
__global__ void gate_kernel(const float* __restrict__ x,
                            const float* __restrict__ gW,
                            const float* __restrict__ gb) {
    int gwarp = (blockIdx.x * blockDim.x + threadIdx.x) >> 5;
    int lane  = threadIdx.x & 31;
    if (gwarp >= Bn) return;
    const float* xr = x + (size_t)gwarp * Dn;
    float acc[En];
#pragma unroll
    for (int e = 0; e < En; e++) acc[e] = 0.0f;
    for (int d = lane; d < Dn; d += 32) {
        float xv = xr[d];
        const float* g = gW + d * En;
#pragma unroll
        for (int e = 0; e < En; e++) acc[e] += xv * g[e];
    }
#pragma unroll
    for (int off = 16; off > 0; off >>= 1)
#pragma unroll
        for (int e = 0; e < En; e++)
            acc[e] += __shfl_down_sync(0xffffffffu, acc[e], off);
    if (lane == 0) {
        float l[En];
#pragma unroll
        for (int e = 0; e < En; e++) l[e] = acc[e] + gb[e];
        float m = l[0];
#pragma unroll
        for (int e = 1; e < En; e++) m = fmaxf(m, l[e]);
        float p[En]; float s = 0.0f;
#pragma unroll
        for (int e = 0; e < En; e++) { p[e] = expf(l[e] - m); s += p[e]; }
        float inv = 1.0f / s;
        int i0 = 0;
#pragma unroll
        for (int e = 1; e < En; e++) if (p[e] > p[i0]) i0 = e;
        int i1 = (i0 == 0) ? 1 : 0;
#pragma unroll
        for (int e = 0; e < En; e++) if (e != i0 && p[e] > p[i1]) i1 = e;
        float gg0 = p[i0] * inv, gg1 = p[i1] * inv;
        float wsum = gg0 + gg1;
        g_top[2 * gwarp]     = i0;
        g_top[2 * gwarp + 1] = i1;
        g_wgt[2 * gwarp]     = gg0 / wsum;
        g_wgt[2 * gwarp + 1] = gg1 / wsum;
        atomicAdd(&g_count[i0], 1);
        atomicAdd(&g_count[i1], 1);
#pragma unroll
        for (int e = 0; e < En; e++) atomicAdd(&g_usage[e], p[e] * inv);
    }
}

__global__ void offsets_kernel() {
    if (threadIdx.x == 0 && blockIdx.x == 0) {
        int o = 0;
        for (int e = 0; e < En; e++) { g_off[e] = o; o += ((g_count[e] + 127) / 128) * 128; }
        g_off[En] = o;
    }
}

__global__ void scatter_kernel() {
    int t = blockIdx.x * blockDim.x + threadIdx.x;
    if (t >= Bn) return;
#pragma unroll
    for (int j = 0; j < KSEL; j++) {
        int e = g_top[2 * t + j];
        int p = atomicAdd(&g_cursor[e], 1);
        int pos = g_off[e] + p;
        g_tok[pos] = t;
        g_slot[2 * t + j] = pos;
    }
}

// ---------------- bf16x3 HMMA GEMM ----------------
// BM=128, BN=128, BK=32; 256 threads, 8 warps (2m x 4n), warp tile 64x32.
// SMEM per stage: Ahi[128][40] Alo[128][40] Bhi[32][136] Blo[32][136] bf16
#define A_STRIDE 40
#define B_STRIDE 136
#define A_PLANE  (128 * A_STRIDE * 2)          // 10240 B
#define B_PLANE  (32 * B_STRIDE * 2)           // 8704 B
#define OFF_ALO  A_PLANE
#define OFF_BHI  (2 * A_PLANE)                 // 20480
#define OFF_BLO  (2 * A_PLANE + B_PLANE)       // 29184
#define STAGE    (2 * A_PLANE + 2 * B_PLANE)   // 37888 B
#define NSTAGE   3
#define GEMM_SMEM (NSTAGE * STAGE)             // 113664 B

template<int KTOT, int NLD, bool IS_G1>
__global__ void __launch_bounds__(256, 1)
moe_gemm_kernel(const __nv_bfloat16* __restrict__ AHg,
                const __nv_bfloat16* __restrict__ ALg,
                const __nv_bfloat16* __restrict__ BHg,
                const __nv_bfloat16* __restrict__ BLg,
                const float* __restrict__ bias,
                float* __restrict__ Cout)   // used when !IS_G1
{
    extern __shared__ char smem[];
    __shared__ int soff[En + 1];
    __shared__ int stok[128];
    const uint32_t sb0 = smem_u32(smem);
    const int tid = threadIdx.x;
    const int lane = tid & 31;
    const int wid = tid >> 5;
    const int wm = wid >> 2;     // 0..1
    const int wn = wid & 3;      // 0..3

    const int m0 = blockIdx.y * 128;
    const int n0 = blockIdx.x * 128;
    if (tid <= En) soff[tid] = g_off[tid];
    if (IS_G1 && tid < 128) stok[tid] = g_tok[m0 + tid];
    __syncthreads();
    if (m0 >= soff[En]) return;
    int e = 0;
    while (m0 >= soff[e + 1]) e++;

    // ---- loader mappings ----
    const int arow = tid >> 1;              // 0..127
    const int ak0  = (tid & 1) * 16;        // {0,16}
    const int brow = tid >> 3;              // 0..31
    const int bn0  = (tid & 7) * 16;        // 0..112
    const size_t arowG = IS_G1 ? (size_t)stok[arow] : (size_t)(m0 + arow);
    const __nv_bfloat16* aH = AHg + arowG * KTOT + ak0;
    const __nv_bfloat16* aL = ALg + arowG * KTOT + ak0;
    const size_t boffG = (size_t)e * KTOT * NLD + (size_t)brow * NLD + n0 + bn0;
    const __nv_bfloat16* bH = BHg + boffG;
    const __nv_bfloat16* bL = BLg + boffG;
    const uint32_t adst = (uint32_t)((arow * A_STRIDE + ak0) * 2);
    const uint32_t bdst = (uint32_t)((brow * B_STRIDE + bn0) * 2);

    auto load_stage = [&](int s, int bs) {
        const uint32_t d = sb0 + bs * STAGE;
        const __nv_bfloat16* sah = aH + s * 32;
        const __nv_bfloat16* sal = aL + s * 32;
        const __nv_bfloat16* sbh = bH + (size_t)s * 32 * NLD;
        const __nv_bfloat16* sbl = bL + (size_t)s * 32 * NLD;
        CP16(d + adst,                sah);     CP16(d + adst + 16,                sah + 8);
        CP16(d + OFF_ALO + adst,      sal);     CP16(d + OFF_ALO + adst + 16,      sal + 8);
        CP16(d + OFF_BHI + bdst,      sbh);     CP16(d + OFF_BHI + bdst + 16,      sbh + 8);
        CP16(d + OFF_BLO + bdst,      sbl);     CP16(d + OFF_BLO + bdst + 16,      sbl + 8);
        CP_COMMIT();
    };

    // ---- mma lane mappings ----
    const uint32_t a_row = (uint32_t)(wm * 64 + (lane & 15));
    const uint32_t a_k   = (uint32_t)((lane >> 4) * 8);
    const uint32_t b_k   = (uint32_t)(lane & 15);
    const uint32_t b_n   = (uint32_t)(wn * 32 + (lane >> 4) * 8);

    float acc[4][4][4];
#pragma unroll
    for (int i = 0; i < 4; i++)
#pragma unroll
        for (int j = 0; j < 4; j++)
#pragma unroll
            for (int q = 0; q < 4; q++) acc[i][j][q] = 0.0f;

    const int S = KTOT / 32;
    load_stage(0, 0);
    load_stage(1, 1);

    int bs = 0;
    for (int s = 0; s < S; s++) {
        if (s + 2 <= S) { CP_WAIT1(); } else { CP_WAIT0(); }
        __syncthreads();

        const uint32_t Ah = sb0 + bs * STAGE;
        const uint32_t Al = Ah + OFF_ALO;
        const uint32_t Bh = Ah + OFF_BHI;
        const uint32_t Bl = Ah + OFF_BLO;
#pragma unroll
        for (int kh = 0; kh < 32; kh += 16) {
            uint32_t ah[4][4], al[4][4], bh[4][2], bl[4][2];
#pragma unroll
            for (int mt = 0; mt < 4; mt++) {
                uint32_t aoff = ((a_row + mt * 16) * A_STRIDE + kh + a_k) * 2;
                LDMX4(ah[mt][0], ah[mt][1], ah[mt][2], ah[mt][3], Ah + aoff);
                LDMX4(al[mt][0], al[mt][1], al[mt][2], al[mt][3], Al + aoff);
            }
#pragma unroll
            for (int ng = 0; ng < 2; ng++) {
                uint32_t boff = ((b_k + kh) * B_STRIDE + b_n + ng * 16) * 2;
                uint32_t q0, q1, q2, q3;
                LDMX4T(q0, q1, q2, q3, Bh + boff);
                bh[2*ng][0] = q0; bh[2*ng][1] = q1; bh[2*ng+1][0] = q2; bh[2*ng+1][1] = q3;
                LDMX4T(q0, q1, q2, q3, Bl + boff);
                bl[2*ng][0] = q0; bl[2*ng][1] = q1; bl[2*ng+1][0] = q2; bl[2*ng+1][1] = q3;
            }
#pragma unroll
            for (int mt = 0; mt < 4; mt++)
#pragma unroll
                for (int nt = 0; nt < 4; nt++) {
                    MMA(acc[mt][nt], ah[mt], bh[nt]);
                    MMA(acc[mt][nt], ah[mt], bl[nt]);
                    MMA(acc[mt][nt], al[mt], bh[nt]);
                }
        }
        __syncthreads();
        if (s + 2 < S) load_stage(s + 2, (s + 2) % NSTAGE);
        bs = (bs + 1) % NSTAGE;
    }

    // ---- epilogue ----
    const float* be = bias + (size_t)e * NLD + n0;
#pragma unroll
    for (int mt = 0; mt < 4; mt++) {
        int r0 = m0 + wm * 64 + mt * 16 + (lane >> 2);
        int r1 = r0 + 8;
#pragma unroll
        for (int nt = 0; nt < 4; nt++) {
            int c = wn * 32 + nt * 8 + (lane & 3) * 2;
            float2 bb = __ldg((const float2*)(be + c));
            float v00 = acc[mt][nt][0] + bb.x, v01 = acc[mt][nt][1] + bb.y;
            float v10 = acc[mt][nt][2] + bb.x, v11 = acc[mt][nt][3] + bb.y;
            if (IS_G1) {
                v00 = fmaxf(v00, 0.0f); v01 = fmaxf(v01, 0.0f);
                v10 = fmaxf(v10, 0.0f); v11 = fmaxf(v11, 0.0f);
                uint32_t h0, l0, h1, l1;
                split2(v00, v01, h0, l0);
                split2(v10, v11, h1, l1);
                *(uint32_t*)&g_hhi[(size_t)r0 * NLD + n0 + c] = h0;
                *(uint32_t*)&g_hlo[(size_t)r0 * NLD + n0 + c] = l0;
                *(uint32_t*)&g_hhi[(size_t)r1 * NLD + n0 + c] = h1;
                *(uint32_t*)&g_hlo[(size_t)r1 * NLD + n0 + c] = l1;
            } else {
                *(float2*)&Cout[(size_t)r0 * NLD + n0 + c] = make_float2(v00, v01);
                *(float2*)&Cout[(size_t)r1 * NLD + n0 + c] = make_float2(v10, v11);
            }
        }
    }
}

// ---------------- combine ----------------
__global__ void combine_kernel(float* __restrict__ out) {
    int idx = blockIdx.x * blockDim.x + threadIdx.x;
    if (idx >= Bn * On) return;
    int t = idx >> 10;
    int o = idx & (On - 1);
    int   s0 = g_slot[2 * t],  s1 = g_slot[2 * t + 1];
    float w0 = g_wgt[2 * t],   w1 = g_wgt[2 * t + 1];
    out[idx] = w0 * g_out[(size_t)s0 * On + o] + w1 * g_out[(size_t)s1 * On + o];
}

// ---------------- per-expert means ----------------
__global__ void avgs_kernel() {
    int e  = blockIdx.x;
    int cb = blockIdx.y * 32;
    int c  = threadIdx.x & 31;
    int rg = threadIdx.x >> 5;
    int off = g_off[e], cnt = g_count[e];
    float s = 0.0f;
    for (int r = rg; r < cnt; r += 8)
        s += g_out[(size_t)(off + r) * On + cb + c];
    __shared__ float red[8][32];
    red[rg][c] = s;
    __syncthreads();
    if (rg == 0) {
        float t = 0.0f;
#pragma unroll
        for (int i = 0; i < 8; i++) t += red[i][c];
        g_avg[e * On + cb + c] = t / (float)max(cnt, 1);
    }
}

// ---------------- losses ----------------
__global__ void loss_kernel(float* __restrict__ out) {
    __shared__ float red[256];
    int tid = threadIdx.x;
    float dl = 0.0f;
    for (int i = 0; i < En; i++) {
        for (int j = i + 1; j < En; j++) {
            float part = 0.0f;
            for (int o = tid; o < On; o += 256) {
                float d = g_avg[i * On + o] - g_avg[j * On + o];
                part += d * d;
            }
            red[tid] = part;
            __syncthreads();
            for (int s = 128; s > 0; s >>= 1) {
                if (tid < s) red[tid] += red[tid + s];
                __syncthreads();
            }
            if (tid == 0 && g_count[i] > 0 && g_count[j] > 0)
                dl += expf(-red[0] * 0.5f);
            __syncthreads();
        }
    }
    if (tid == 0) {
        out[(size_t)Bn * On] = dl;
        float eq = 0.0f;
        for (int e = 0; e < En; e++) {
            float u = g_usage[e] / (float)Bn - 1.0f / (float)En;
            eq += u * u;
        }
        out[(size_t)Bn * On + 1] = sqrtf(eq);
    }
}

// ---------------- launch ----------------
extern "C" void kernel_launch(void* const* d_in, const int* in_sizes, int n_in,
                              void* d_out, int out_size) {
    (void)in_sizes; (void)n_in; (void)out_size;
    const float* x  = (const float*)d_in[0];
    const float* gW = (const float*)d_in[1];
    const float* gb = (const float*)d_in[2];
    const float* W1 = (const float*)d_in[3];
    const float* b1 = (const float*)d_in[4];
    const float* W2 = (const float*)d_in[5];
    const float* b2 = (const float*)d_in[6];
    float* out = (float*)d_out;

    cudaFuncSetAttribute(moe_gemm_kernel<Dn, Hn, true>,
                         cudaFuncAttributeMaxDynamicSharedMemorySize, GEMM_SMEM);
    cudaFuncSetAttribute(moe_gemm_kernel<Hn, On, false>,
                         cudaFuncAttributeMaxDynamicSharedMemorySize, GEMM_SMEM);

    // resolve __device__ plane pointers for kernel args
    __nv_bfloat16 *xhi, *xlo, *w1hi, *w1lo, *w2hi, *w2lo, *hhi, *hlo;
    cudaGetSymbolAddress((void**)&xhi,  g_xhi);
    cudaGetSymbolAddress((void**)&xlo,  g_xlo);
    cudaGetSymbolAddress((void**)&w1hi, g_w1hi);
    cudaGetSymbolAddress((void**)&w1lo, g_w1lo);
    cudaGetSymbolAddress((void**)&w2hi, g_w2hi);
    cudaGetSymbolAddress((void**)&w2lo, g_w2lo);
    cudaGetSymbolAddress((void**)&hhi,  g_hhi);
    cudaGetSymbolAddress((void**)&hlo,  g_hlo);
    float* outbuf;
    cudaGetSymbolAddress((void**)&outbuf, g_out);

    init_kernel<<<(CAP + 255) / 256, 256>>>();
    gate_kernel<<<Bn / 8, 256>>>(x, gW, gb);
    offsets_kernel<<<1, 32>>>();
    scatter_kernel<<<Bn / 256, 256>>>();

    convert_kernel<<<(Bn * Dn / 4 + 255) / 256, 256>>>(x, xhi, xlo, Bn * Dn / 4);
    convert_kernel<<<(En * Dn * Hn / 4 + 255) / 256, 256>>>(W1, w1hi, w1lo, En * Dn * Hn / 4);
    convert_kernel<<<(En * Hn * On / 4 + 255) / 256, 256>>>(W2, w2hi, w2lo, En * Hn * On / 4);

    moe_gemm_kernel<Dn, Hn, true><<<dim3(Hn / 128, CAP / 128), 256, GEMM_SMEM>>>(
        xhi, xlo, w1hi, w1lo, b1, nullptr);
    moe_gemm_kernel<Hn, On, false><<<dim3(On / 128, CAP / 128), 256, GEMM_SMEM>>>(
        hhi, hlo, w2hi, w2lo, b2, outbuf);

    combine_kernel<<<(Bn * On) / 256, 256>>>(out);
    avgs_kernel<<<dim3(En, On / 32), 256>>>();
    loss_kernel<<<1, 256>>>(out);
}

// round 5
// speedup vs baseline: 2.7452x; 1.4530x over previous
#include <cuda_runtime.h>
#include <cuda_fp16.h>
#include <math.h>
#include <stdint.h>

// Problem constants
#define Bn   8192
#define Dn   1024
#define Hn   4096
#define On   1024
#define En   8
#define KSEL 2
#define CAP  (Bn*KSEL + En*128)   // 17408

// ---------------- device scratch ----------------
__device__ int   g_top[Bn * 2];
__device__ float g_wgt[Bn * 2];
__device__ float g_usage[En];
__device__ int   g_count[En];
__device__ int   g_cursor[En];
__device__ int   g_off[En + 1];
__device__ int   g_tok[CAP];
__device__ int   g_slot[Bn * 2];
__device__ float g_out[(size_t)CAP * On];
__device__ float g_avg[En * On];
// fp16 planes: A operands get hi+lo (error-compensated), weights hi only
__device__ __half g_xhi[(size_t)Bn * Dn];
__device__ __half g_xlo[(size_t)Bn * Dn];
__device__ __half g_w1h[(size_t)En * Dn * Hn];
__device__ __half g_w2h[(size_t)En * Hn * On];
__device__ __half g_hhi[(size_t)CAP * Hn];
__device__ __half g_hlo[(size_t)CAP * Hn];

// ---------------- asm helpers ----------------
__device__ __forceinline__ uint32_t smem_u32(const void* p) {
    uint32_t a;
    asm("{ .reg .u64 t; cvta.to.shared.u64 t, %1; cvt.u32.u64 %0, t; }" : "=r"(a) : "l"(p));
    return a;
}
#define CP16(dst, src) \
    asm volatile("cp.async.cg.shared.global [%0], [%1], 16;" \
                 :: "r"(dst), "l"(__cvta_generic_to_global(src)) : "memory")
#define CP_COMMIT() asm volatile("cp.async.commit_group;" ::: "memory")
#define CP_WAIT1()  asm volatile("cp.async.wait_group 1;" ::: "memory")
#define CP_WAIT0()  asm volatile("cp.async.wait_group 0;" ::: "memory")

#define LDMX4(r0,r1,r2,r3,addr) \
    asm volatile("ldmatrix.sync.aligned.m8n8.x4.shared.b16 {%0,%1,%2,%3}, [%4];" \
                 : "=r"(r0),"=r"(r1),"=r"(r2),"=r"(r3) : "r"(addr))
#define LDMX4T(r0,r1,r2,r3,addr) \
    asm volatile("ldmatrix.sync.aligned.m8n8.x4.trans.shared.b16 {%0,%1,%2,%3}, [%4];" \
                 : "=r"(r0),"=r"(r1),"=r"(r2),"=r"(r3) : "r"(addr))
#define MMA(d,a,b0,b1) \
    asm volatile("mma.sync.aligned.m16n8k16.row.col.f32.f16.f16.f32 " \
                 "{%0,%1,%2,%3},{%4,%5,%6,%7},{%8,%9},{%0,%1,%2,%3};" \
                 : "+f"((d)[0]),"+f"((d)[1]),"+f"((d)[2]),"+f"((d)[3]) \
                 : "r"((a)[0]),"r"((a)[1]),"r"((a)[2]),"r"((a)[3]), \
                   "r"(b0),"r"(b1))

__device__ __forceinline__ void split2h(float a, float b, uint32_t& hi, uint32_t& lo) {
    __half2 h = __floats2half2_rn(a, b);
    float ra = a - __half2float(__low2half(h));
    float rb = b - __half2float(__high2half(h));
    __half2 l = __floats2half2_rn(ra, rb);
    hi = *(uint32_t*)&h; lo = *(uint32_t*)&l;
}

// ---------------- init ----------------
__global__ void init_kernel() {
    int idx = blockIdx.x * blockDim.x + threadIdx.x;
    if (idx < CAP) g_tok[idx] = 0;
    if (idx < En) { g_count[idx] = 0; g_cursor[idx] = 0; g_usage[idx] = 0.0f; }
}

// ---------------- fp32 -> fp16 hi/lo (2-plane) ----------------
__global__ void convert2h_kernel(const float* __restrict__ src,
                                 __half* __restrict__ hi,
                                 __half* __restrict__ lo, int n4) {
    int i = blockIdx.x * blockDim.x + threadIdx.x;
    if (i >= n4) return;
    float4 v = __ldg((const float4*)src + i);
    uint32_t h01, l01, h23, l23;
    split2h(v.x, v.y, h01, l01);
    split2h(v.z, v.w, h23, l23);
    ((uint2*)hi)[i] = make_uint2(h01, h23);
    ((uint2*)lo)[i] = make_uint2(l01, l23);
}
// ---------------- fp32 -> fp16 (1-plane, weights) ----------------
__global__ void convert1h_kernel(const float* __restrict__ src,
                                 __half* __restrict__ hi, int n4) {
    int i = blockIdx.x * blockDim.x + threadIdx.x;
    if (i >= n4) return;
    float4 v = __ldg((const float4*)src + i);
    __half2 h01 = __floats2half2_rn(v.x, v.y);
    __half2 h23 = __floats2half2_rn(v.z, v.w);
    ((uint2*)hi)[i] = make_uint2(*(uint32_t*)&h01, *(uint32_t*)&h23);
}

// ---------------- gating: one warp per token ----------------
__global__ void gate_kernel(const float* __restrict__ x,
                            const float* __restrict__ gW,
                            const float* __restrict__ gb) {
    int gwarp = (blockIdx.x * blockDim.x + threadIdx.x) >> 5;
    int lane  = threadIdx.x & 31;
    if (gwarp >= Bn) return;
    const float* xr = x + (size_t)gwarp * Dn;
    float acc[En];
#pragma unroll
    for (int e = 0; e < En; e++) acc[e] = 0.0f;
    for (int d = lane; d < Dn; d += 32) {
        float xv = xr[d];
        const float* g = gW + d * En;
#pragma unroll
        for (int e = 0; e < En; e++) acc[e] += xv * g[e];
    }
#pragma unroll
    for (int off = 16; off > 0; off >>= 1)
#pragma unroll
        for (int e = 0; e < En; e++)
            acc[e] += __shfl_down_sync(0xffffffffu, acc[e], off);
    if (lane == 0) {
        float l[En];
#pragma unroll
        for (int e = 0; e < En; e++) l[e] = acc[e] + gb[e];
        float m = l[0];
#pragma unroll
        for (int e = 1; e < En; e++) m = fmaxf(m, l[e]);
        float p[En]; float s = 0.0f;
#pragma unroll
        for (int e = 0; e < En; e++) { p[e] = expf(l[e] - m); s += p[e]; }
        float inv = 1.0f / s;
        int i0 = 0;
#pragma unroll
        for (int e = 1; e < En; e++) if (p[e] > p[i0]) i0 = e;
        int i1 = (i0 == 0) ? 1 : 0;
#pragma unroll
        for (int e = 0; e < En; e++) if (e != i0 && p[e] > p[i1]) i1 = e;
        float gg0 = p[i0] * inv, gg1 = p[i1] * inv;
        float wsum = gg0 + gg1;
        g_top[2 * gwarp]     = i0;
        g_top[2 * gwarp + 1] = i1;
        g_wgt[2 * gwarp]     = gg0 / wsum;
        g_wgt[2 * gwarp + 1] = gg1 / wsum;
        atomicAdd(&g_count[i0], 1);
        atomicAdd(&g_count[i1], 1);
#pragma unroll
        for (int e = 0; e < En; e++) atomicAdd(&g_usage[e], p[e] * inv);
    }
}

__global__ void offsets_kernel() {
    if (threadIdx.x == 0 && blockIdx.x == 0) {
        int o = 0;
        for (int e = 0; e < En; e++) { g_off[e] = o; o += ((g_count[e] + 127) / 128) * 128; }
        g_off[En] = o;
    }
}

__global__ void scatter_kernel() {
    int t = blockIdx.x * blockDim.x + threadIdx.x;
    if (t >= Bn) return;
#pragma unroll
    for (int j = 0; j < KSEL; j++) {
        int e = g_top[2 * t + j];
        int p = atomicAdd(&g_cursor[e], 1);
        int pos = g_off[e] + p;
        g_tok[pos] = t;
        g_slot[2 * t + j] = pos;
    }
}

// ---------------- fp16x2 HMMA GEMM ----------------
// BM=128, BN=256, BK=32; 256 threads, 8 warps (2m x 4n), warp tile 64x64.
// A: hi+lo planes (fp16), B: hi only. 2 MMAs per logical op.
#define A_ST 40                      // halves per A row (32 + 8 pad)
#define B_ST 264                     // halves per B row (256 + 8 pad)
#define A_PL (128 * A_ST * 2)        // 10240 B
#define B_PL (32 * B_ST * 2)         // 16896 B
#define OFF_ALO A_PL
#define OFF_B   (2 * A_PL)           // 20480
#define STAGE   (2 * A_PL + B_PL)    // 37376 B
#define NSTAGE  3
#define GEMM_SMEM (NSTAGE * STAGE)   // 112128 B

template<int KTOT, int NLD, bool IS_G1>
__global__ void __launch_bounds__(256, 1)
moe_gemm_kernel(const __half* __restrict__ AHg,
                const __half* __restrict__ ALg,
                const __half* __restrict__ BHg,
                const float* __restrict__ bias,
                float* __restrict__ Cout)
{
    extern __shared__ char smem[];
    __shared__ int soff[En + 1];
    __shared__ int stok[128];
    const uint32_t sb0 = smem_u32(smem);
    const int tid = threadIdx.x;
    const int lane = tid & 31;
    const int wid = tid >> 5;
    const int wm = wid >> 2;     // 0..1
    const int wn = wid & 3;      // 0..3

    const int m0 = blockIdx.y * 128;
    const int n0 = blockIdx.x * 256;
    if (tid <= En) soff[tid] = g_off[tid];
    if (IS_G1 && tid < 128) stok[tid] = g_tok[m0 + tid];
    __syncthreads();
    if (m0 >= soff[En]) return;
    int e = 0;
    while (m0 >= soff[e + 1]) e++;

    // ---- loader mappings ----
    const int arow = tid >> 1;              // 0..127
    const int ak0  = (tid & 1) * 16;        // {0,16} halves
    const int brow = tid >> 3;              // 0..31
    const int bc0  = (tid & 7) * 32;        // 0..224 halves
    const size_t arowG = IS_G1 ? (size_t)stok[arow] : (size_t)(m0 + arow);
    const __half* aH = AHg + arowG * KTOT + ak0;
    const __half* aL = ALg + arowG * KTOT + ak0;
    const __half* bH = BHg + (size_t)e * KTOT * NLD + (size_t)brow * NLD + n0 + bc0;
    const uint32_t adst = (uint32_t)((arow * A_ST + ak0) * 2);
    const uint32_t bdst = (uint32_t)((brow * B_ST + bc0) * 2);

    auto load_stage = [&](int s, int bs) {
        const uint32_t d = sb0 + bs * STAGE;
        const __half* sah = aH + s * 32;
        const __half* sal = aL + s * 32;
        const __half* sbh = bH + (size_t)s * 32 * NLD;
        CP16(d + adst,           sah);  CP16(d + adst + 16,           sah + 8);
        CP16(d + OFF_ALO + adst, sal);  CP16(d + OFF_ALO + adst + 16, sal + 8);
#pragma unroll
        for (int j = 0; j < 4; j++)
            CP16(d + OFF_B + bdst + j * 16, sbh + j * 8);
        CP_COMMIT();
    };

    // ---- mma lane mappings ----
    const uint32_t a_row = (uint32_t)(wm * 64 + (lane & 15));
    const uint32_t a_k   = (uint32_t)((lane >> 4) * 8);
    const uint32_t b_k   = (uint32_t)(lane & 15);
    const uint32_t b_n   = (uint32_t)(wn * 64 + (lane >> 4) * 8);

    float acc[4][8][4];
#pragma unroll
    for (int i = 0; i < 4; i++)
#pragma unroll
        for (int j = 0; j < 8; j++)
#pragma unroll
            for (int q = 0; q < 4; q++) acc[i][j][q] = 0.0f;

    const int S = KTOT / 32;
    load_stage(0, 0);
    load_stage(1, 1);

    int bs = 0;
    for (int s = 0; s < S; s++) {
        if (s + 2 <= S) { CP_WAIT1(); } else { CP_WAIT0(); }
        __syncthreads();

        const uint32_t Ah = sb0 + bs * STAGE;
        const uint32_t Al = Ah + OFF_ALO;
        const uint32_t Bh = Ah + OFF_B;
#pragma unroll
        for (int kh = 0; kh < 32; kh += 16) {
            uint32_t ah[4][4], al[4][4];
#pragma unroll
            for (int mt = 0; mt < 4; mt++) {
                uint32_t aoff = ((a_row + mt * 16) * A_ST + kh + a_k) * 2;
                LDMX4(ah[mt][0], ah[mt][1], ah[mt][2], ah[mt][3], Ah + aoff);
                LDMX4(al[mt][0], al[mt][1], al[mt][2], al[mt][3], Al + aoff);
            }
#pragma unroll
            for (int ng = 0; ng < 4; ng++) {
                uint32_t boff = ((b_k + kh) * B_ST + b_n + ng * 16) * 2;
                uint32_t q0, q1, q2, q3;
                LDMX4T(q0, q1, q2, q3, Bh + boff);
#pragma unroll
                for (int mt = 0; mt < 4; mt++) {
                    MMA(acc[mt][2 * ng],     ah[mt], q0, q1);
                    MMA(acc[mt][2 * ng],     al[mt], q0, q1);
                    MMA(acc[mt][2 * ng + 1], ah[mt], q2, q3);
                    MMA(acc[mt][2 * ng + 1], al[mt], q2, q3);
                }
            }
        }
        __syncthreads();
        if (s + 2 < S) load_stage(s + 2, (s + 2) % NSTAGE);
        bs = (bs + 1) % NSTAGE;
    }

    // ---- epilogue ----
    const float* be = bias + (size_t)e * NLD + n0;
#pragma unroll
    for (int mt = 0; mt < 4; mt++) {
        int r0 = m0 + wm * 64 + mt * 16 + (lane >> 2);
        int r1 = r0 + 8;
#pragma unroll
        for (int nt = 0; nt < 8; nt++) {
            int c = wn * 64 + nt * 8 + (lane & 3) * 2;
            float2 bb = __ldg((const float2*)(be + c));
            float v00 = acc[mt][nt][0] + bb.x, v01 = acc[mt][nt][1] + bb.y;
            float v10 = acc[mt][nt][2] + bb.x, v11 = acc[mt][nt][3] + bb.y;
            if (IS_G1) {
                v00 = fmaxf(v00, 0.0f); v01 = fmaxf(v01, 0.0f);
                v10 = fmaxf(v10, 0.0f); v11 = fmaxf(v11, 0.0f);
                uint32_t h0, l0, h1, l1;
                split2h(v00, v01, h0, l0);
                split2h(v10, v11, h1, l1);
                *(uint32_t*)&g_hhi[(size_t)r0 * NLD + n0 + c] = h0;
                *(uint32_t*)&g_hlo[(size_t)r0 * NLD + n0 + c] = l0;
                *(uint32_t*)&g_hhi[(size_t)r1 * NLD + n0 + c] = h1;
                *(uint32_t*)&g_hlo[(size_t)r1 * NLD + n0 + c] = l1;
            } else {
                *(float2*)&Cout[(size_t)r0 * NLD + n0 + c] = make_float2(v00, v01);
                *(float2*)&Cout[(size_t)r1 * NLD + n0 + c] = make_float2(v10, v11);
            }
        }
    }
}

// ---------------- combine ----------------
__global__ void combine_kernel(float* __restrict__ out) {
    int idx = blockIdx.x * blockDim.x + threadIdx.x;
    if (idx >= Bn * On) return;
    int t = idx >> 10;
    int o = idx & (On - 1);
    int   s0 = g_slot[2 * t],  s1 = g_slot[2 * t + 1];
    float w0 = g_wgt[2 * t],   w1 = g_wgt[2 * t + 1];
    out[idx] = w0 * g_out[(size_t)s0 * On + o] + w1 * g_out[(size_t)s1 * On + o];
}

// ---------------- per-expert means ----------------
__global__ void avgs_kernel() {
    int e  = blockIdx.x;
    int cb = blockIdx.y * 32;
    int c  = threadIdx.x & 31;
    int rg = threadIdx.x >> 5;
    int off = g_off[e], cnt = g_count[e];
    float s = 0.0f;
    for (int r = rg; r < cnt; r += 8)
        s += g_out[(size_t)(off + r) * On + cb + c];
    __shared__ float red[8][32];
    red[rg][c] = s;
    __syncthreads();
    if (rg == 0) {
        float t = 0.0f;
#pragma unroll
        for (int i = 0; i < 8; i++) t += red[i][c];
        g_avg[e * On + cb + c] = t / (float)max(cnt, 1);
    }
}

// ---------------- losses ----------------
__global__ void loss_kernel(float* __restrict__ out) {
    __shared__ float red[256];
    int tid = threadIdx.x;
    float dl = 0.0f;
    for (int i = 0; i < En; i++) {
        for (int j = i + 1; j < En; j++) {
            float part = 0.0f;
            for (int o = tid; o < On; o += 256) {
                float d = g_avg[i * On + o] - g_avg[j * On + o];
                part += d * d;
            }
            red[tid] = part;
            __syncthreads();
            for (int s = 128; s > 0; s >>= 1) {
                if (tid < s) red[tid] += red[tid + s];
                __syncthreads();
            }
            if (tid == 0 && g_count[i] > 0 && g_count[j] > 0)
                dl += expf(-red[0] * 0.5f);
            __syncthreads();
        }
    }
    if (tid == 0) {
        out[(size_t)Bn * On] = dl;
        float eq = 0.0f;
        for (int e = 0; e < En; e++) {
            float u = g_usage[e] / (float)Bn - 1.0f / (float)En;
            eq += u * u;
        }
        out[(size_t)Bn * On + 1] = sqrtf(eq);
    }
}

// ---------------- launch ----------------
extern "C" void kernel_launch(void* const* d_in, const int* in_sizes, int n_in,
                              void* d_out, int out_size) {
    (void)in_sizes; (void)n_in; (void)out_size;
    const float* x  = (const float*)d_in[0];
    const float* gW = (const float*)d_in[1];
    const float* gb = (const float*)d_in[2];
    const float* W1 = (const float*)d_in[3];
    const float* b1 = (const float*)d_in[4];
    const float* W2 = (const float*)d_in[5];
    const float* b2 = (const float*)d_in[6];
    float* out = (float*)d_out;

    cudaFuncSetAttribute(moe_gemm_kernel<Dn, Hn, true>,
                         cudaFuncAttributeMaxDynamicSharedMemorySize, GEMM_SMEM);
    cudaFuncSetAttribute(moe_gemm_kernel<Hn, On, false>,
                         cudaFuncAttributeMaxDynamicSharedMemorySize, GEMM_SMEM);

    __half *xhi, *xlo, *w1h, *w2h, *hhi, *hlo;
    cudaGetSymbolAddress((void**)&xhi, g_xhi);
    cudaGetSymbolAddress((void**)&xlo, g_xlo);
    cudaGetSymbolAddress((void**)&w1h, g_w1h);
    cudaGetSymbolAddress((void**)&w2h, g_w2h);
    cudaGetSymbolAddress((void**)&hhi, g_hhi);
    cudaGetSymbolAddress((void**)&hlo, g_hlo);
    float* outbuf;
    cudaGetSymbolAddress((void**)&outbuf, g_out);

    init_kernel<<<(CAP + 255) / 256, 256>>>();
    gate_kernel<<<Bn / 8, 256>>>(x, gW, gb);
    offsets_kernel<<<1, 32>>>();
    scatter_kernel<<<Bn / 256, 256>>>();

    convert2h_kernel<<<(Bn * Dn / 4 + 255) / 256, 256>>>(x, xhi, xlo, Bn * Dn / 4);
    convert1h_kernel<<<(En * Dn * Hn / 4 + 255) / 256, 256>>>(W1, w1h, En * Dn * Hn / 4);
    convert1h_kernel<<<(En * Hn * On / 4 + 255) / 256, 256>>>(W2, w2h, En * Hn * On / 4);

    moe_gemm_kernel<Dn, Hn, true><<<dim3(Hn / 256, CAP / 128), 256, GEMM_SMEM>>>(
        xhi, xlo, w1h, b1, nullptr);
    moe_gemm_kernel<Hn, On, false><<<dim3(On / 256, CAP / 128), 256, GEMM_SMEM>>>(
        hhi, hlo, w2h, b2, outbuf);

    combine_kernel<<<(Bn * On) / 256, 256>>>(out);
    avgs_kernel<<<dim3(En, On / 32), 256>>>();
    loss_kernel<<<1, 256>>>(out);
}

// round 6
// speedup vs baseline: 3.9193x; 1.4277x over previous
#include <cuda_runtime.h>
#include <cuda_fp16.h>
#include <math.h>
#include <stdint.h>

// Problem constants
#define Bn   8192
#define Dn   1024
#define Hn   4096
#define On   1024
#define En   8
#define KSEL 2
#define CAP  (Bn*KSEL + En*128)   // 17408

// ---------------- device scratch ----------------
__device__ int   g_top[Bn * 2];
__device__ float g_wgt[Bn * 2];
__device__ float g_usage[En];
__device__ int   g_count[En];
__device__ int   g_cursor[En];
__device__ int   g_off[En + 1];
__device__ int   g_tok[CAP];
__device__ int   g_slot[Bn * 2];
__device__ float g_out[(size_t)CAP * On];
__device__ float g_avg[En * On];
// single fp16 planes
__device__ __half g_xh[(size_t)Bn * Dn];
__device__ __half g_w1h[(size_t)En * Dn * Hn];
__device__ __half g_w2h[(size_t)En * Hn * On];
__device__ __half g_hh[(size_t)CAP * Hn];

// ---------------- asm helpers ----------------
__device__ __forceinline__ uint32_t smem_u32(const void* p) {
    uint32_t a;
    asm("{ .reg .u64 t; cvta.to.shared.u64 t, %1; cvt.u32.u64 %0, t; }" : "=r"(a) : "l"(p));
    return a;
}
#define CP16(dst, src) \
    asm volatile("cp.async.cg.shared.global [%0], [%1], 16;" \
                 :: "r"(dst), "l"(__cvta_generic_to_global(src)) : "memory")
#define CP_COMMIT() asm volatile("cp.async.commit_group;" ::: "memory")
#define CP_WAIT1()  asm volatile("cp.async.wait_group 1;" ::: "memory")
#define CP_WAIT0()  asm volatile("cp.async.wait_group 0;" ::: "memory")

#define LDMX4(r0,r1,r2,r3,addr) \
    asm volatile("ldmatrix.sync.aligned.m8n8.x4.shared.b16 {%0,%1,%2,%3}, [%4];" \
                 : "=r"(r0),"=r"(r1),"=r"(r2),"=r"(r3) : "r"(addr))
#define LDMX4T(r0,r1,r2,r3,addr) \
    asm volatile("ldmatrix.sync.aligned.m8n8.x4.trans.shared.b16 {%0,%1,%2,%3}, [%4];" \
                 : "=r"(r0),"=r"(r1),"=r"(r2),"=r"(r3) : "r"(addr))
#define MMA(d,a,b0,b1) \
    asm volatile("mma.sync.aligned.m16n8k16.row.col.f32.f16.f16.f32 " \
                 "{%0,%1,%2,%3},{%4,%5,%6,%7},{%8,%9},{%0,%1,%2,%3};" \
                 : "+f"((d)[0]),"+f"((d)[1]),"+f"((d)[2]),"+f"((d)[3]) \
                 : "r"((a)[0]),"r"((a)[1]),"r"((a)[2]),"r"((a)[3]), \
                   "r"(b0),"r"(b1))

// ---------------- init ----------------
__global__ void init_kernel() {
    int idx = blockIdx.x * blockDim.x + threadIdx.x;
    if (idx < CAP) g_tok[idx] = 0;
    if (idx < En) { g_count[idx] = 0; g_cursor[idx] = 0; g_usage[idx] = 0.0f; }
}

// ---------------- fp32 -> fp16 (1 plane) ----------------
__global__ void convert1h_kernel(const float* __restrict__ src,
                                 __half* __restrict__ hi, int n4) {
    int i = blockIdx.x * blockDim.x + threadIdx.x;
    if (i >= n4) return;
    float4 v = __ldg((const float4*)src + i);
    __half2 h01 = __floats2half2_rn(v.x, v.y);
    __half2 h23 = __floats2half2_rn(v.z, v.w);
    ((uint2*)hi)[i] = make_uint2(*(uint32_t*)&h01, *(uint32_t*)&h23);
}

// ---------------- gating: one warp per token ----------------
__global__ void gate_kernel(const float* __restrict__ x,
                            const float* __restrict__ gW,
                            const float* __restrict__ gb) {
    int gwarp = (blockIdx.x * blockDim.x + threadIdx.x) >> 5;
    int lane  = threadIdx.x & 31;
    if (gwarp >= Bn) return;
    const float* xr = x + (size_t)gwarp * Dn;
    float acc[En];
#pragma unroll
    for (int e = 0; e < En; e++) acc[e] = 0.0f;
    for (int d = lane; d < Dn; d += 32) {
        float xv = xr[d];
        const float* g = gW + d * En;
#pragma unroll
        for (int e = 0; e < En; e++) acc[e] += xv * g[e];
    }
#pragma unroll
    for (int off = 16; off > 0; off >>= 1)
#pragma unroll
        for (int e = 0; e < En; e++)
            acc[e] += __shfl_down_sync(0xffffffffu, acc[e], off);
    if (lane == 0) {
        float l[En];
#pragma unroll
        for (int e = 0; e < En; e++) l[e] = acc[e] + gb[e];
        float m = l[0];
#pragma unroll
        for (int e = 1; e < En; e++) m = fmaxf(m, l[e]);
        float p[En]; float s = 0.0f;
#pragma unroll
        for (int e = 0; e < En; e++) { p[e] = expf(l[e] - m); s += p[e]; }
        float inv = 1.0f / s;
        int i0 = 0;
#pragma unroll
        for (int e = 1; e < En; e++) if (p[e] > p[i0]) i0 = e;
        int i1 = (i0 == 0) ? 1 : 0;
#pragma unroll
        for (int e = 0; e < En; e++) if (e != i0 && p[e] > p[i1]) i1 = e;
        float gg0 = p[i0] * inv, gg1 = p[i1] * inv;
        float wsum = gg0 + gg1;
        g_top[2 * gwarp]     = i0;
        g_top[2 * gwarp + 1] = i1;
        g_wgt[2 * gwarp]     = gg0 / wsum;
        g_wgt[2 * gwarp + 1] = gg1 / wsum;
        atomicAdd(&g_count[i0], 1);
        atomicAdd(&g_count[i1], 1);
#pragma unroll
        for (int e = 0; e < En; e++) atomicAdd(&g_usage[e], p[e] * inv);
    }
}

__global__ void offsets_kernel() {
    if (threadIdx.x == 0 && blockIdx.x == 0) {
        int o = 0;
        for (int e = 0; e < En; e++) { g_off[e] = o; o += ((g_count[e] + 127) / 128) * 128; }
        g_off[En] = o;
    }
}

__global__ void scatter_kernel() {
    int t = blockIdx.x * blockDim.x + threadIdx.x;
    if (t >= Bn) return;
#pragma unroll
    for (int j = 0; j < KSEL; j++) {
        int e = g_top[2 * t + j];
        int p = atomicAdd(&g_cursor[e], 1);
        int pos = g_off[e] + p;
        g_tok[pos] = t;
        g_slot[2 * t + j] = pos;
    }
}

// ---------------- fp16 HMMA GEMM (1 MMA / logical op) ----------------
// BM=128, BN=256, BK=32; 256 threads, 8 warps (2m x 4n), warp tile 64x64.
#define A_ST 40                      // halves per A row (32 + 8 pad)
#define B_ST 264                     // halves per B row (256 + 8 pad)
#define A_PL (128 * A_ST * 2)        // 10240 B
#define B_PL (32 * B_ST * 2)         // 16896 B
#define OFF_B   A_PL                 // 10240
#define STAGE   (A_PL + B_PL)        // 27136 B
#define NSTAGE  3
#define GEMM_SMEM (NSTAGE * STAGE)   // 81408 B

template<int KTOT, int NLD, bool IS_G1>
__global__ void __launch_bounds__(256, 1)
moe_gemm_kernel(const __half* __restrict__ AHg,
                const __half* __restrict__ BHg,
                const float* __restrict__ bias,
                float* __restrict__ Cout)
{
    extern __shared__ char smem[];
    __shared__ int soff[En + 1];
    __shared__ int stok[128];
    const uint32_t sb0 = smem_u32(smem);
    const int tid = threadIdx.x;
    const int lane = tid & 31;
    const int wid = tid >> 5;
    const int wm = wid >> 2;     // 0..1
    const int wn = wid & 3;      // 0..3

    const int m0 = blockIdx.y * 128;
    const int n0 = blockIdx.x * 256;
    if (tid <= En) soff[tid] = g_off[tid];
    if (IS_G1 && tid < 128) stok[tid] = g_tok[m0 + tid];
    __syncthreads();
    if (m0 >= soff[En]) return;
    int e = 0;
    while (m0 >= soff[e + 1]) e++;

    // ---- loader mappings ----
    const int arow = tid >> 1;              // 0..127
    const int ak0  = (tid & 1) * 16;        // {0,16} halves
    const int brow = tid >> 3;              // 0..31
    const int bc0  = (tid & 7) * 32;        // 0..224 halves
    const size_t arowG = IS_G1 ? (size_t)stok[arow] : (size_t)(m0 + arow);
    const __half* aH = AHg + arowG * KTOT + ak0;
    const __half* bH = BHg + (size_t)e * KTOT * NLD + (size_t)brow * NLD + n0 + bc0;
    const uint32_t adst = (uint32_t)((arow * A_ST + ak0) * 2);
    const uint32_t bdst = (uint32_t)((brow * B_ST + bc0) * 2);

    auto load_stage = [&](int s, int bs) {
        const uint32_t d = sb0 + bs * STAGE;
        const __half* sah = aH + s * 32;
        const __half* sbh = bH + (size_t)s * 32 * NLD;
        CP16(d + adst, sah);  CP16(d + adst + 16, sah + 8);
#pragma unroll
        for (int j = 0; j < 4; j++)
            CP16(d + OFF_B + bdst + j * 16, sbh + j * 8);
        CP_COMMIT();
    };

    // ---- mma lane mappings ----
    const uint32_t a_row = (uint32_t)(wm * 64 + (lane & 15));
    const uint32_t a_k   = (uint32_t)((lane >> 4) * 8);
    const uint32_t b_k   = (uint32_t)(lane & 15);
    const uint32_t b_n   = (uint32_t)(wn * 64 + (lane >> 4) * 8);

    float acc[4][8][4];
#pragma unroll
    for (int i = 0; i < 4; i++)
#pragma unroll
        for (int j = 0; j < 8; j++)
#pragma unroll
            for (int q = 0; q < 4; q++) acc[i][j][q] = 0.0f;

    const int S = KTOT / 32;
    load_stage(0, 0);
    load_stage(1, 1);

    int bs = 0;
    for (int s = 0; s < S; s++) {
        if (s + 2 <= S) { CP_WAIT1(); } else { CP_WAIT0(); }
        __syncthreads();

        const uint32_t Ah = sb0 + bs * STAGE;
        const uint32_t Bh = Ah + OFF_B;
#pragma unroll
        for (int kh = 0; kh < 32; kh += 16) {
            uint32_t ah[4][4];
#pragma unroll
            for (int mt = 0; mt < 4; mt++) {
                uint32_t aoff = ((a_row + mt * 16) * A_ST + kh + a_k) * 2;
                LDMX4(ah[mt][0], ah[mt][1], ah[mt][2], ah[mt][3], Ah + aoff);
            }
#pragma unroll
            for (int ng = 0; ng < 4; ng++) {
                uint32_t boff = ((b_k + kh) * B_ST + b_n + ng * 16) * 2;
                uint32_t q0, q1, q2, q3;
                LDMX4T(q0, q1, q2, q3, Bh + boff);
#pragma unroll
                for (int mt = 0; mt < 4; mt++) {
                    MMA(acc[mt][2 * ng],     ah[mt], q0, q1);
                    MMA(acc[mt][2 * ng + 1], ah[mt], q2, q3);
                }
            }
        }
        __syncthreads();
        if (s + 2 < S) load_stage(s + 2, (s + 2) % NSTAGE);
        bs = (bs + 1) % NSTAGE;
    }

    // ---- epilogue ----
    const float* be = bias + (size_t)e * NLD + n0;
#pragma unroll
    for (int mt = 0; mt < 4; mt++) {
        int r0 = m0 + wm * 64 + mt * 16 + (lane >> 2);
        int r1 = r0 + 8;
#pragma unroll
        for (int nt = 0; nt < 8; nt++) {
            int c = wn * 64 + nt * 8 + (lane & 3) * 2;
            float2 bb = __ldg((const float2*)(be + c));
            float v00 = acc[mt][nt][0] + bb.x, v01 = acc[mt][nt][1] + bb.y;
            float v10 = acc[mt][nt][2] + bb.x, v11 = acc[mt][nt][3] + bb.y;
            if (IS_G1) {
                v00 = fmaxf(v00, 0.0f); v01 = fmaxf(v01, 0.0f);
                v10 = fmaxf(v10, 0.0f); v11 = fmaxf(v11, 0.0f);
                __half2 h0 = __floats2half2_rn(v00, v01);
                __half2 h1 = __floats2half2_rn(v10, v11);
                *(uint32_t*)&g_hh[(size_t)r0 * NLD + n0 + c] = *(uint32_t*)&h0;
                *(uint32_t*)&g_hh[(size_t)r1 * NLD + n0 + c] = *(uint32_t*)&h1;
            } else {
                *(float2*)&Cout[(size_t)r0 * NLD + n0 + c] = make_float2(v00, v01);
                *(float2*)&Cout[(size_t)r1 * NLD + n0 + c] = make_float2(v10, v11);
            }
        }
    }
}

// ---------------- combine ----------------
__global__ void combine_kernel(float* __restrict__ out) {
    int idx = blockIdx.x * blockDim.x + threadIdx.x;
    if (idx >= Bn * On) return;
    int t = idx >> 10;
    int o = idx & (On - 1);
    int   s0 = g_slot[2 * t],  s1 = g_slot[2 * t + 1];
    float w0 = g_wgt[2 * t],   w1 = g_wgt[2 * t + 1];
    out[idx] = w0 * g_out[(size_t)s0 * On + o] + w1 * g_out[(size_t)s1 * On + o];
}

// ---------------- per-expert means ----------------
__global__ void avgs_kernel() {
    int e  = blockIdx.x;
    int cb = blockIdx.y * 32;
    int c  = threadIdx.x & 31;
    int rg = threadIdx.x >> 5;
    int off = g_off[e], cnt = g_count[e];
    float s = 0.0f;
    for (int r = rg; r < cnt; r += 8)
        s += g_out[(size_t)(off + r) * On + cb + c];
    __shared__ float red[8][32];
    red[rg][c] = s;
    __syncthreads();
    if (rg == 0) {
        float t = 0.0f;
#pragma unroll
        for (int i = 0; i < 8; i++) t += red[i][c];
        g_avg[e * On + cb + c] = t / (float)max(cnt, 1);
    }
}

// ---------------- losses ----------------
__global__ void loss_kernel(float* __restrict__ out) {
    __shared__ float red[256];
    int tid = threadIdx.x;
    float dl = 0.0f;
    for (int i = 0; i < En; i++) {
        for (int j = i + 1; j < En; j++) {
            float part = 0.0f;
            for (int o = tid; o < On; o += 256) {
                float d = g_avg[i * On + o] - g_avg[j * On + o];
                part += d * d;
            }
            red[tid] = part;
            __syncthreads();
            for (int s = 128; s > 0; s >>= 1) {
                if (tid < s) red[tid] += red[tid + s];
                __syncthreads();
            }
            if (tid == 0 && g_count[i] > 0 && g_count[j] > 0)
                dl += expf(-red[0] * 0.5f);
            __syncthreads();
        }
    }
    if (tid == 0) {
        out[(size_t)Bn * On] = dl;
        float eq = 0.0f;
        for (int e = 0; e < En; e++) {
            float u = g_usage[e] / (float)Bn - 1.0f / (float)En;
            eq += u * u;
        }
        out[(size_t)Bn * On + 1] = sqrtf(eq);
    }
}

// ---------------- launch ----------------
extern "C" void kernel_launch(void* const* d_in, const int* in_sizes, int n_in,
                              void* d_out, int out_size) {
    (void)in_sizes; (void)n_in; (void)out_size;
    const float* x  = (const float*)d_in[0];
    const float* gW = (const float*)d_in[1];
    const float* gb = (const float*)d_in[2];
    const float* W1 = (const float*)d_in[3];
    const float* b1 = (const float*)d_in[4];
    const float* W2 = (const float*)d_in[5];
    const float* b2 = (const float*)d_in[6];
    float* out = (float*)d_out;

    cudaFuncSetAttribute(moe_gemm_kernel<Dn, Hn, true>,
                         cudaFuncAttributeMaxDynamicSharedMemorySize, GEMM_SMEM);
    cudaFuncSetAttribute(moe_gemm_kernel<Hn, On, false>,
                         cudaFuncAttributeMaxDynamicSharedMemorySize, GEMM_SMEM);

    __half *xh, *w1h, *w2h, *hh;
    cudaGetSymbolAddress((void**)&xh,  g_xh);
    cudaGetSymbolAddress((void**)&w1h, g_w1h);
    cudaGetSymbolAddress((void**)&w2h, g_w2h);
    cudaGetSymbolAddress((void**)&hh,  g_hh);
    float* outbuf;
    cudaGetSymbolAddress((void**)&outbuf, g_out);

    init_kernel<<<(CAP + 255) / 256, 256>>>();
    gate_kernel<<<Bn / 8, 256>>>(x, gW, gb);
    offsets_kernel<<<1, 32>>>();
    scatter_kernel<<<Bn / 256, 256>>>();

    convert1h_kernel<<<(Bn * Dn / 4 + 255) / 256, 256>>>(x, xh, Bn * Dn / 4);
    convert1h_kernel<<<(En * Dn * Hn / 4 + 255) / 256, 256>>>(W1, w1h, En * Dn * Hn / 4);
    convert1h_kernel<<<(En * Hn * On / 4 + 255) / 256, 256>>>(W2, w2h, En * Hn * On / 4);

    moe_gemm_kernel<Dn, Hn, true><<<dim3(Hn / 256, CAP / 128), 256, GEMM_SMEM>>>(
        xh, w1h, b1, nullptr);
    moe_gemm_kernel<Hn, On, false><<<dim3(On / 256, CAP / 128), 256, GEMM_SMEM>>>(
        hh, w2h, b2, outbuf);

    combine_kernel<<<(Bn * On) / 256, 256>>>(out);
    avgs_kernel<<<dim3(En, On / 32), 256>>>();
    loss_kernel<<<1, 256>>>(out);
}